// round 8
// baseline (speedup 1.0000x reference)
#include <cuda_runtime.h>
#include <cuda_fp16.h>
#include <math.h>
#include <stdint.h>

// Problem constants
#define T_     128
#define NSEQ   256          // B*S
#define EMBED  512
#define UNITS  512
#define G4     2048         // 4*UNITS
#define NZ     4096         // both directions
#define NCTA   128
#define GSZ    16           // CTAs per dependency group (dir, rb)

// ---------------- scratch (device globals) ---------------------------------
__device__ __half   g_xW[(size_t)NSEQ * T_ * NZ];  // fp16 [s*T+t][4096] fwd|bwd, bias incl
__device__ __half   g_h16[2][2][NSEQ * UNITS];     // fp16 h, [parity][dir]
__device__ uint32_t g_Upk[2 * 16 * 32768];         // fp16 frag-packed U per (dir,cb) slice
__device__ uint32_t g_Wpk[32 * 32768];             // fp16 frag-packed [W_f|W_b] per 128-col slice

struct alignas(128) Bar { unsigned cnt; unsigned gen; };
__device__ Bar g_bars[8];                          // one per (dir, rb) group

__device__ __forceinline__ float tanh_fast(float x) {
    float r; asm("tanh.approx.f32 %0, %1;" : "=f"(r) : "f"(x)); return r;
}
__device__ __forceinline__ float sigm_fast(float x) {
    return fmaf(tanh_fast(0.5f * x), 0.5f, 0.5f);
}

// ---------------- pack U into fp16 MMA-fragment order ----------------------
__global__ __launch_bounds__(256) void prep_U(
    const float* __restrict__ U_f, const float* __restrict__ U_b)
{
    int widx  = blockIdx.x * 256 + threadIdx.x;   // < 2^20
    int word  = widx & 32767;
    int slice = widx >> 15;
    int dir = slice >> 4, cb = slice & 15;
    int kb   = word >> 10;
    int np   = (word >> 7) & 7;
    int lane = (word >> 2) & 31;
    int q    = word & 3;
    int sub = q >> 1, wi = q & 1;
    int qr = lane >> 2, qc = lane & 3;
    int n = (np * 2 + sub) * 8 + qr;
    int k = kb * 16 + wi * 8 + 2 * qc;
    int col = (n >> 5) * 512 + cb * 32 + (n & 31);
    const float* U = dir ? U_b : U_f;
    float lo = U[(size_t)k * G4 + col];
    float hi = U[(size_t)(k + 1) * G4 + col];
    half2 h2 = __floats2half2_rn(lo, hi);
    g_Upk[widx] = *(uint32_t*)&h2;
}

// ---------------- pack [W_f|W_b] into same fragment order ------------------
__global__ __launch_bounds__(256) void prep_W(
    const float* __restrict__ W_f, const float* __restrict__ W_b)
{
    int widx  = blockIdx.x * 256 + threadIdx.x;   // < 2^20
    int word  = widx & 32767;
    int nb    = widx >> 15;
    int kb   = word >> 10;
    int np   = (word >> 7) & 7;
    int lane = (word >> 2) & 31;
    int q    = word & 3;
    int sub = q >> 1, wi = q & 1;
    int qr = lane >> 2, qc = lane & 3;
    int nl = (np * 2 + sub) * 8 + qr;
    int k  = kb * 16 + wi * 8 + 2 * qc;
    int c  = nb * 128 + nl;
    const float* W = (c < G4) ? (W_f + c) : (W_b + c - G4);
    float lo = W[(size_t)k * G4];
    float hi = W[(size_t)(k + 1) * G4];
    half2 h2 = __floats2half2_rn(lo, hi);
    g_Wpk[widx] = *(uint32_t*)&h2;
}

// ---------------- MMA helpers ----------------------------------------------
#define MMA16816(d, a, b0v, b1v)                                              \
    asm volatile(                                                             \
        "mma.sync.aligned.m16n8k16.row.col.f32.f16.f16.f32 "                  \
        "{%0,%1,%2,%3},{%4,%5,%6,%7},{%8,%9},{%0,%1,%2,%3};"                  \
        : "+f"(d[0]), "+f"(d[1]), "+f"(d[2]), "+f"(d[3])                      \
        : "r"(a[0]), "r"(a[1]), "r"(a[2]), "r"(a[3]), "r"(b0v), "r"(b1v))

#define LDSM4(r, addr)                                                        \
    asm volatile("ldmatrix.sync.aligned.m8n8.x4.shared.b16 "                  \
                 "{%0,%1,%2,%3}, [%4];"                                       \
                 : "=r"(r[0]), "=r"(r[1]), "=r"(r[2]), "=r"(r[3])             \
                 : "r"(addr))

extern __shared__ char smem_dyn[];

// ---------------- Phase 1: fused gather + fp16 tensor-core GEMM ------------
#define ESTR 520   // A staging row stride in halves (padded layout)

__global__ __launch_bounds__(256, 1) void embed_mma(
    const int* __restrict__ x, const float* __restrict__ emb,
    const float* __restrict__ b_f, const float* __restrict__ b_b)
{
    __shared__ int ids_s[128];
    __half* hA = (__half*)smem_dyn;                // 128 x ESTR halves

    const int tid  = threadIdx.x;
    const int lane = tid & 31;
    const int wid  = tid >> 5;
    const int wm   = wid >> 1;          // 0..3 : 32 rows
    const int wn   = wid & 1;           // 0..1 : 128 cols
    const int qr = lane >> 2, qc = lane & 3;
    const int mBase = blockIdx.y * 128;
    const int nb    = blockIdx.x * 2 + wn;

    if (tid < 128) ids_s[tid] = x[mBase + tid];
    __syncthreads();

    // Stage full A tile: 128 rows x 512 k, fp32 -> fp16
    {
        int row = tid >> 1, seg = tid & 1;
        const float* src = emb + (size_t)ids_s[row] * EMBED + seg * 256;
        __half* d = hA + row * ESTR + seg * 256;
        #pragma unroll
        for (int i = 0; i < 64; i++) {
            float4 v = *(const float4*)(src + i * 4);
            *(half2*)(d + i * 4)     = __floats2half2_rn(v.x, v.y);
            *(half2*)(d + i * 4 + 2) = __floats2half2_rn(v.z, v.w);
        }
    }
    __syncthreads();

    int lm_row = (lane & 7) + ((lane >> 3) & 1) * 8;
    int lm_kh  = (lane >> 4) * 8;
    uint32_t hA_s = (uint32_t)__cvta_generic_to_shared(hA);
    uint32_t lmaddr0 = hA_s + (uint32_t)(((wm * 32 + 0  + lm_row) * ESTR + lm_kh) * 2);
    uint32_t lmaddr1 = hA_s + (uint32_t)(((wm * 32 + 16 + lm_row) * ESTR + lm_kh) * 2);

    const uint32_t* gW = g_Wpk + (size_t)nb * 32768;

    float acc[2][16][4];
    #pragma unroll
    for (int mt = 0; mt < 2; mt++)
        #pragma unroll
        for (int j = 0; j < 16; j++)
            #pragma unroll
            for (int r = 0; r < 4; r++) acc[mt][j][r] = 0.f;

    #pragma unroll 2
    for (int kb = 0; kb < 32; kb++) {
        uint32_t a0[4], a1[4];
        LDSM4(a0, lmaddr0 + kb * 32);
        LDSM4(a1, lmaddr1 + kb * 32);
        uint4 Bv[8];
        #pragma unroll
        for (int np = 0; np < 8; np++)
            Bv[np] = *(const uint4*)&gW[(((kb * 8 + np) * 32 + lane) << 2)];
        #pragma unroll
        for (int j = 0; j < 16; j++) {
            uint32_t b0 = (j & 1) ? Bv[j >> 1].z : Bv[j >> 1].x;
            uint32_t b1 = (j & 1) ? Bv[j >> 1].w : Bv[j >> 1].y;
            MMA16816(acc[0][j], a0, b0, b1);
            MMA16816(acc[1][j], a1, b0, b1);
        }
    }

    // Epilogue: add bias, store fp16 z to g_xW
    const float* bp = (nb < 16) ? (b_f + nb * 128) : (b_b + nb * 128 - G4);
    #pragma unroll
    for (int mt = 0; mt < 2; mt++) {
        #pragma unroll
        for (int j = 0; j < 16; j++) {
            int row = mBase + wm * 32 + mt * 16 + qr;
            int cl  = j * 8 + qc * 2;
            float bx = bp[cl], by = bp[cl + 1];
            half2 lo = __floats2half2_rn(acc[mt][j][0] + bx, acc[mt][j][1] + by);
            half2 hi = __floats2half2_rn(acc[mt][j][2] + bx, acc[mt][j][3] + by);
            *(half2*)&g_xW[(size_t)row * NZ + nb * 128 + cl]       = lo;
            *(half2*)&g_xW[(size_t)(row + 8) * NZ + nb * 128 + cl] = hi;
        }
    }
}

// ---------------- Phase 2: persistent bidirectional LSTM -------------------
// 128 CTAs x 512 thr. CTA (dir, cb, rb): 64 rows x 128 zcols.
// Warp (wm, wn): 16 rows x 8 hcols, ALL 4 gates in-thread (n8-tile j = g*4+wn)
// -> no SMEM z exchange; epilogue on registers with MUFU tanh.approx.
__global__ __launch_bounds__(512, 1) void lstm_persist(
    const int* __restrict__ x, float* __restrict__ out)
{
    uint32_t* uB  = (uint32_t*)smem_dyn;           // 128 KB
    char*     hAb = smem_dyn + 131072;             // 64 KB swizzled A staging

    const int tid  = threadIdx.x;
    const int lane = tid & 31;
    const int wid  = tid >> 5;                     // 0..15
    const int bid  = blockIdx.x;
    const int dir  = bid >> 6;
    const int cb   = (bid >> 2) & 15;
    const int rb   = bid & 3;
    const int gid  = dir * 4 + rb;
    const int rBase  = rb * 64;
    const int cbBase = cb * 32;

    // Load U slice once (resident for all steps)
    {
        const uint4* src = (const uint4*)(g_Upk + (size_t)(dir * 16 + cb) * 32768);
        uint4* dst = (uint4*)uB;
        #pragma unroll
        for (int i = 0; i < 16; i++) dst[i * 512 + tid] = src[i * 512 + tid];
    }

    const int wm = wid >> 2;          // 0..3 : 16 rows
    const int wn = wid & 3;           // 0..3 : 8 hcols each
    const int qr = lane >> 2, qc = lane & 3;
    const int woff = wn >> 1;         // np offset
    const int sub2 = (wn & 1) * 2;    // word-pair offset within uint4

    // This thread's cells: rows s0,s1 = rBase + wm*16 + qr (+8),
    // hcols hc0 = cbBase + wn*8 + 2qc (+1). All 4 gates in-register.
    const int hc = wn * 8 + 2 * qc;   // local hcol within 32-block

    // Register-resident state: [e(row) * 2 + cc(col)]
    float creg[4], hreg[4];
    #pragma unroll
    for (int e = 0; e < 4; e++) { creg[e] = 0.f; hreg[e] = 0.f; }
    // Zero h16[0] slice (this CTA's cells)
    #pragma unroll
    for (int e = 0; e < 2; e++) {
        int row = rBase + wm * 16 + qr + e * 8;
        *(half2*)&g_h16[0][dir][row * UNITS + cbBase + hc] = __floats2half2_rn(0.f, 0.f);
    }

    // ldmatrix swizzled base: addr(kb) = C0 ^ (kb*32)
    const int lrow = wm * 16 + (lane & 7) + ((lane >> 3) & 1) * 8;
    const int hi   = lane >> 4;
    const int r7   = lrow & 7;
    uint32_t hA_s = (uint32_t)__cvta_generic_to_shared(hAb);
    const uint32_t C0 = hA_s + (uint32_t)(lrow * 1024 + ((hi ^ (r7 & 1)) * 16) + (r7 >> 1) * 32);

    // staging thread mapping
    const int srow = tid >> 3, ssub = tid & 7, sr7 = srow & 7;

    unsigned curgen = 0;   // tid0 only: barrier generation snapshot

    float2 xwf[2][4];      // [row e][gate] prefetched xW
    bool   mreg[2];

    for (int sstep = 0; sstep < T_; sstep++) {
        const int parity = sstep & 1;
        const int t = dir ? (T_ - 1 - sstep) : sstep;
        const __half* h16cur = g_h16[parity][dir];
        __half*       h16nxt = g_h16[parity ^ 1][dir];

        // ---- barrier arrive (publishes prev step's h / init zeros) ----
        __syncthreads();
        if (tid == 0) {
            __threadfence();
            volatile unsigned* genp = &g_bars[gid].gen;
            curgen = *genp;
            if (atomicAdd(&g_bars[gid].cnt, 1u) == GSZ - 1) {
                g_bars[gid].cnt = 0;
                __threadfence();
                *genp = curgen + 1;
            }
        }

        // ---- prefetch this step's xW + mask (overlaps barrier wait) ----
        #pragma unroll
        for (int e = 0; e < 2; e++) {
            int s = rBase + wm * 16 + qr + e * 8;
            const __half* p = g_xW + ((size_t)s * T_ + t) * NZ + dir * G4 + cbBase + hc;
            #pragma unroll
            for (int g = 0; g < 4; g++)
                xwf[e][g] = __half22float2(*(const half2*)(p + g * 512));
            mreg[e] = (x[s * T_ + t] != 0);
        }

        // ---- barrier wait ----
        if (tid == 0) {
            volatile unsigned* genp = &g_bars[gid].gen;
            while (*genp == curgen) { __nanosleep(20); }
            __threadfence();
        }
        __syncthreads();

        // ---- stage h tile (64 rows x 512 halves) -> swizzled SMEM ----
        {
            const __half* src = h16cur + (size_t)(rBase + srow) * UNITS;
            #pragma unroll
            for (int i = 0; i < 8; i++) {
                int u = i * 8 + ssub;
                uint4 v = *(const uint4*)(src + u * 8);
                *(uint4*)(hAb + srow * 1024 + ((u ^ sr7) * 16)) = v;
            }
        }
        __syncthreads();

        // ---- K loop: z = h @ U; acc[g] = gate g's n8-tile ----
        float acc[4][4];
        #pragma unroll
        for (int g = 0; g < 4; g++)
            #pragma unroll
            for (int r = 0; r < 4; r++) acc[g][r] = 0.f;

        #pragma unroll 8
        for (int kb = 0; kb < 32; kb++) {
            uint32_t a0[4];
            LDSM4(a0, C0 ^ (uint32_t)(kb << 5));
            #pragma unroll
            for (int g = 0; g < 4; g++) {
                uint2 bv = *(const uint2*)&uB[(((kb * 8 + g * 2 + woff) * 32 + lane) << 2) + sub2];
                MMA16816(acc[g], a0, bv.x, bv.y);
            }
        }

        // ---- fused gate epilogue on registers; write h fp16 for peers ----
        #pragma unroll
        for (int e = 0; e < 2; e++) {
            float hv[2];
            #pragma unroll
            for (int cc = 0; cc < 2; cc++) {
                int idx = e * 2 + cc;
                float zi = acc[0][idx] + (cc ? xwf[e][0].y : xwf[e][0].x);
                float zf = acc[1][idx] + (cc ? xwf[e][1].y : xwf[e][1].x);
                float zg = acc[2][idx] + (cc ? xwf[e][2].y : xwf[e][2].x);
                float zo = acc[3][idx] + (cc ? xwf[e][3].y : xwf[e][3].x);
                float ig = sigm_fast(zi), fg = sigm_fast(zf);
                float gg = tanh_fast(zg), og = sigm_fast(zo);
                float cnew = fg * creg[idx] + ig * gg;
                float hnew = og * tanh_fast(cnew);
                if (mreg[e]) { creg[idx] = cnew; hreg[idx] = hnew; }
                hv[cc] = hreg[idx];
            }
            int row = rBase + wm * 16 + qr + e * 8;
            *(half2*)&h16nxt[row * UNITS + cbBase + hc] = __floats2half2_rn(hv[0], hv[1]);
        }
    }

    // Output straight from registers
    #pragma unroll
    for (int e = 0; e < 2; e++) {
        int s = rBase + wm * 16 + qr + e * 8;
        *(float2*)&out[s * 1024 + dir * 512 + cbBase + hc] =
            make_float2(hreg[e * 2], hreg[e * 2 + 1]);
    }
}

// ---------------- launcher -------------------------------------------------
extern "C" void kernel_launch(void* const* d_in, const int* in_sizes, int n_in,
                              void* d_out, int out_size)
{
    const int*   x   = (const int*)  d_in[0];
    const float* emb = (const float*)d_in[1];
    const float* W_f = (const float*)d_in[2];
    const float* U_f = (const float*)d_in[3];
    const float* b_f = (const float*)d_in[4];
    const float* W_b = (const float*)d_in[5];
    const float* U_b = (const float*)d_in[6];
    const float* b_b = (const float*)d_in[7];
    float* out = (float*)d_out;

    cudaFuncSetAttribute(embed_mma,
                         cudaFuncAttributeMaxDynamicSharedMemorySize, 133120);
    cudaFuncSetAttribute(lstm_persist,
                         cudaFuncAttributeMaxDynamicSharedMemorySize, 196608);

    prep_U<<<(2 * 16 * 32768) / 256, 256>>>(U_f, U_b);
    prep_W<<<(32 * 32768) / 256, 256>>>(W_f, W_b);
    embed_mma<<<dim3(16, 256), 256, 133120>>>(x, emb, b_f, b_b);
    lstm_persist<<<NCTA, 512, 196608>>>(x, out);
}